// round 7
// baseline (speedup 1.0000x reference)
#include <cuda_runtime.h>
#include <cuda_bf16.h>
#include <mma.h>
#include <math.h>
#include <stdint.h>

using namespace nvcuda;

#define HW   4096
#define WD   64
#define C    256
#define B    16
#define NO   260   // 256 ctx channels + 4 gate channels

// ---------------- scratch (static device globals; no allocs) ----------------
__device__ float g_t[B * NO * HW];       // conv1x1 output: ctx(256, no bias) + gates(4, biased)
__device__ float g_ctxall[B * C * HW];   // ctx_all
__device__ float g_klog[B * HW];
__device__ float g_k[B * HW];
__device__ float g_qk[B * C];
__device__ float g_v[B * C];
__device__ __align__(16) __nv_bfloat16 g_wh[C * C];      // w hi split (ctx rows)
__device__ __align__(16) __nv_bfloat16 g_wl[C * C];      // w lo split

// ---------------- f32x2 helpers ---------------------------------------------
__device__ __forceinline__ unsigned long long pk2(float lo, float hi) {
    unsigned long long r;
    asm("mov.b64 %0,{%1,%2};" : "=l"(r) : "f"(lo), "f"(hi));
    return r;
}
__device__ __forceinline__ void upk2(unsigned long long v, float& lo, float& hi) {
    asm("mov.b64 {%0,%1},%2;" : "=f"(lo), "=f"(hi) : "l"(v));
}
__device__ __forceinline__ void fma2(unsigned long long& d, unsigned long long a,
                                     unsigned long long b) {
    asm("fma.rn.f32x2 %0,%1,%2,%0;" : "+l"(d) : "l"(a), "l"(b));
}

// ---------------- cp.async helpers -----------------------------------------
__device__ __forceinline__ unsigned s2u(const void* p) {
    return (unsigned)__cvta_generic_to_shared(p);
}
__device__ __forceinline__ void cp16(unsigned dst, const void* src) {
    asm volatile("cp.async.ca.shared.global [%0], [%1], 16;" :: "r"(dst), "l"(src));
}
#define CP_COMMIT() asm volatile("cp.async.commit_group;")
#define CP_WAIT1()  asm volatile("cp.async.wait_group 1;")

// =====================================================================
// K0: split w (ctx rows 0..255) into bf16 hi/lo
// =====================================================================
__global__ __launch_bounds__(256) void k_wsplit(const float* __restrict__ w) {
    int idx = blockIdx.x * 256 + threadIdx.x;
    float v = w[idx];
    __nv_bfloat16 h = __float2bfloat16(v);
    g_wh[idx] = h;
    g_wl[idx] = __float2bfloat16(v - __bfloat162float(h));
}

// =====================================================================
// K1: wmma bf16 GEMM (3-product hi/lo split), in-kernel x conversion.
// =====================================================================
#define BUF_ELEMS 18944
#define OFF_AL 5120
#define OFF_BH 10240
#define OFF_BL 14592
#define GEMM_SMEM (2 * BUF_ELEMS * 2)   // 75776 bytes

__global__ __launch_bounds__(256, 2) void k_gemm(const float* __restrict__ x) {
    extern __shared__ __align__(16) __nv_bfloat16 sm[];
    const int tid = threadIdx.x;
    const int wid = tid >> 5;
    const int bx = blockIdx.x;
    const int pw = bx & 31, oh = (bx >> 5) & 1, b = bx >> 6;
    const int px0 = pw << 7, o0 = oh << 7;
    const int wm = wid & 1, wn = wid >> 1;

    wmma::fragment<wmma::accumulator, 16, 16, 16, float> acc[4][2];
#pragma unroll
    for (int i = 0; i < 4; i++)
#pragma unroll
        for (int j = 0; j < 2; j++) wmma::fill_fragment(acc[i][j], 0.f);

    auto stageA = [&](int ci) {
        unsigned base = s2u(sm + (ci & 1) * BUF_ELEMS);
        const int k0 = ci << 5;
#pragma unroll
        for (int v = 0; v < 2; v++) {
            const __nv_bfloat16* wsrc = v ? g_wl : g_wh;
#pragma unroll
            for (int it = 0; it < 2; it++) {
                int idx = tid + it * 256;
                int o = idx >> 2, u = idx & 3;
                cp16(base + (unsigned)((v * OFF_AL + o * 40 + u * 8) * 2),
                     wsrc + (o0 + o) * 256 + k0 + u * 8);
            }
        }
    };
    auto ldx = [&](float4* R, int ci) {
        const int k0 = ci << 5;
#pragma unroll
        for (int it = 0; it < 4; it++) {
            int fi = it * 256 + tid;
            int k = fi >> 5, u = fi & 31;
            R[it] = *(const float4*)(x + (((size_t)(b * C + k0 + k)) << 12) + px0 + u * 4);
        }
    };
    auto stsB = [&](const float4* R, int buf) {
        __nv_bfloat16* bp = sm + buf * BUF_ELEMS;
#pragma unroll
        for (int it = 0; it < 4; it++) {
            int fi = it * 256 + tid;
            int k = fi >> 5, u = fi & 31;
            float4 v = R[it];
            __nv_bfloat16 h0 = __float2bfloat16(v.x), h1 = __float2bfloat16(v.y);
            __nv_bfloat16 h2 = __float2bfloat16(v.z), h3 = __float2bfloat16(v.w);
            __nv_bfloat162 hp0 = {h0, h1}, hp1 = {h2, h3};
            __nv_bfloat162 lp0 = {__float2bfloat16(v.x - __bfloat162float(h0)),
                                  __float2bfloat16(v.y - __bfloat162float(h1))};
            __nv_bfloat162 lp1 = {__float2bfloat16(v.z - __bfloat162float(h2)),
                                  __float2bfloat16(v.w - __bfloat162float(h3))};
            uint2 hv = {*(uint32_t*)&hp0, *(uint32_t*)&hp1};
            uint2 lv = {*(uint32_t*)&lp0, *(uint32_t*)&lp1};
            *(uint2*)(bp + OFF_BH + k * 136 + u * 4) = hv;
            *(uint2*)(bp + OFF_BL + k * 136 + u * 4) = lv;
        }
    };
    auto compute = [&](int ci) {
        const __nv_bfloat16* bufp = sm + (ci & 1) * BUF_ELEMS;
        const __nv_bfloat16* AH = bufp;
        const __nv_bfloat16* AL = bufp + OFF_AL;
        const __nv_bfloat16* BH = bufp + OFF_BH;
        const __nv_bfloat16* BL = bufp + OFF_BL;
#pragma unroll
        for (int kk = 0; kk < 2; kk++) {
            wmma::fragment<wmma::matrix_a, 16, 16, 16, __nv_bfloat16, wmma::row_major> af[4];
            wmma::fragment<wmma::matrix_b, 16, 16, 16, __nv_bfloat16, wmma::row_major> bhf[2], blf[2];
#pragma unroll
            for (int j = 0; j < 2; j++)
                wmma::load_matrix_sync(bhf[j], BH + kk * 16 * 136 + wn * 32 + j * 16, 136);
#pragma unroll
            for (int i = 0; i < 4; i++)
                wmma::load_matrix_sync(af[i], AH + (wm * 64 + i * 16) * 40 + kk * 16, 40);
#pragma unroll
            for (int i = 0; i < 4; i++)
#pragma unroll
                for (int j = 0; j < 2; j++)
                    wmma::mma_sync(acc[i][j], af[i], bhf[j], acc[i][j]);
#pragma unroll
            for (int j = 0; j < 2; j++)
                wmma::load_matrix_sync(blf[j], BL + kk * 16 * 136 + wn * 32 + j * 16, 136);
#pragma unroll
            for (int i = 0; i < 4; i++)
#pragma unroll
                for (int j = 0; j < 2; j++)
                    wmma::mma_sync(acc[i][j], af[i], blf[j], acc[i][j]);
#pragma unroll
            for (int i = 0; i < 4; i++)
                wmma::load_matrix_sync(af[i], AL + (wm * 64 + i * 16) * 40 + kk * 16, 40);
#pragma unroll
            for (int i = 0; i < 4; i++)
#pragma unroll
                for (int j = 0; j < 2; j++)
                    wmma::mma_sync(acc[i][j], af[i], bhf[j], acc[i][j]);
        }
    };

    float4 R[4];
    stageA(0);
    CP_COMMIT();
    ldx(R, 0);
    for (int ci = 0; ci < 8; ci++) {
        if (ci < 7) stageA(ci + 1);
        CP_COMMIT();
        CP_WAIT1();
        stsB(R, ci & 1);
        __syncthreads();
        if (ci < 7) ldx(R, ci + 1);
        compute(ci);
        __syncthreads();
    }
#pragma unroll
    for (int i = 0; i < 4; i++)
#pragma unroll
        for (int j = 0; j < 2; j++)
            wmma::store_matrix_sync(
                g_t + (((size_t)(b * NO + o0 + wm * 64 + i * 16)) << 12) + px0 + wn * 32 + j * 16,
                acc[i][j], HW, wmma::mem_row_major);
}

// =====================================================================
// K1b: gate outputs (o = 256..259), 4-way channel split
// =====================================================================
__global__ __launch_bounds__(256) void k_gates(const float* __restrict__ x,
                                               const float* __restrict__ w,
                                               const float* __restrict__ bias) {
    __shared__ float wg[C][4];
    __shared__ float red[4][4][64];
    const int tid = threadIdx.x;
    for (int i = tid; i < C * 4; i += 256) {
        int c = i >> 2, j = i & 3;
        wg[c][j] = w[(256 + j) * C + c];
    }
    __syncthreads();
    const int b   = blockIdx.x >> 6;
    const int px0 = (blockIdx.x & 63) << 6;
    const int pxi = tid & 63;
    const int q   = tid >> 6;
    const float* p = x + (((size_t)(b * C + q * 64)) << 12) + px0 + pxi;
    float a0 = 0.f, a1 = 0.f, a2 = 0.f, a3 = 0.f;
#pragma unroll 8
    for (int c = 0; c < 64; c++) {
        float xv = p[(size_t)c << 12];
        a0 += xv * wg[q * 64 + c][0];
        a1 += xv * wg[q * 64 + c][1];
        a2 += xv * wg[q * 64 + c][2];
        a3 += xv * wg[q * 64 + c][3];
    }
    red[q][0][pxi] = a0;
    red[q][1][pxi] = a1;
    red[q][2][pxi] = a2;
    red[q][3][pxi] = a3;
    __syncthreads();
    if (q == 0) {
#pragma unroll
        for (int j = 0; j < 4; j++) {
            float s = red[0][j][pxi] + red[1][j][pxi] + red[2][j][pxi] + red[3][j][pxi]
                      + bias[256 + j];
            g_t[(((size_t)(b * NO + 256 + j)) << 12) + px0 + pxi] = s;
        }
    }
}

// =====================================================================
// K2: dw3->gelu -> dw5->gelu -> dw7->gelu chain, 2 CHANNELS PER CTA via
// f32x2 (float2-interleaved planes). Lane map lr=lane&15, lc=lane>>4 ->
// conflict-free LDS.64 with PST=71. Dynamic smem 79.5KB, 2 CTA/SM.
// =====================================================================
__device__ __forceinline__ float gelu_exact(float v) {
    return 0.5f * v * (1.f + erff(v * 0.70710678118654752440f));
}

#define PST 71
#define PLANE2 (70 * PST)        // 4970 float2 per buffer
#define DW_SMEM (2 * PLANE2 * 8) // 79520 bytes

template <int KS>
__device__ __forceinline__ void stage2(const float2* __restrict__ s_in,
                                       float2* __restrict__ s_out,
                                       const float2* __restrict__ sW,
                                       int r, int cs) {
    const int P = KS / 2;
    unsigned long long acc[16];
#pragma unroll
    for (int i = 0; i < 16; i++) acc[i] = 0ull;
#pragma unroll
    for (int dy = 0; dy < KS; dy++) {
        unsigned long long row[16 + 2 * (KS / 2)];
        const float2* rp = &s_in[(r + 3 + dy - P) * PST + (cs + 3 - P)];
#pragma unroll
        for (int i = 0; i < 16 + 2 * P; i++) row[i] = *(const unsigned long long*)&rp[i];
#pragma unroll
        for (int dx = 0; dx < KS; dx++) {
            unsigned long long wv = *(const unsigned long long*)&sW[dy * KS + dx];
#pragma unroll
            for (int i = 0; i < 16; i++) fma2(acc[i], row[i + dx], wv);
        }
    }
    float2* op = &s_out[(r + 3) * PST + cs + 3];
#pragma unroll
    for (int i = 0; i < 16; i++) {
        float lo, hi;
        upk2(acc[i], lo, hi);
        op[i] = make_float2(gelu_exact(lo), gelu_exact(hi));
    }
}

__global__ __launch_bounds__(256) void k_dwchain(const float* __restrict__ fw3,
                                                 const float* __restrict__ fw5,
                                                 const float* __restrict__ fw7,
                                                 const float* __restrict__ cb) {
    extern __shared__ __align__(16) float2 dsm[];
    float2* sA = dsm;
    float2* sB = dsm + PLANE2;
    __shared__ float2 sW[49];
    __shared__ float2 sRed[8];
    const int tid = threadIdx.x;
    const int b   = blockIdx.x >> 7;
    const int ch0 = (blockIdx.x & 127) << 1;
    const int wrp  = tid >> 5;
    const int lane = tid & 31;
    const int lr = lane & 15, lc = lane >> 4;
    const int r  = (wrp & 3) * 16 + lr;              // 0..63
    const int cs = (((wrp >> 2) << 1) + lc) << 4;    // 0,16,32,48

    for (int i = tid; i < 2 * PLANE2; i += 256) dsm[i] = make_float2(0.f, 0.f);
    __syncthreads();

    const float bv0 = cb[ch0], bv1 = cb[ch0 + 1];
    const float* s0 = &g_t[(size_t)(b * NO + ch0) << 12];
    const float* s1 = s0 + HW;
#pragma unroll
    for (int i = 0; i < 4; i++) {
        int idx4 = tid + i * 256;                    // 0..1023
        int rr = idx4 >> 4;
        int c4 = (idx4 & 15) << 2;
        float4 a = *(const float4*)(s0 + rr * 64 + c4);
        float4 bb = *(const float4*)(s1 + rr * 64 + c4);
        float2* dst = &sA[(rr + 3) * PST + c4 + 3];
        dst[0] = make_float2(a.x + bv0, bb.x + bv1);
        dst[1] = make_float2(a.y + bv0, bb.y + bv1);
        dst[2] = make_float2(a.z + bv0, bb.z + bv1);
        dst[3] = make_float2(a.w + bv0, bb.w + bv1);
    }

    const float* gbase = &g_t[(size_t)(b * NO + C) << 12];
    unsigned long long accAll[16];
#pragma unroll
    for (int i = 0; i < 16; i++) accAll[i] = 0ull;

    // ---- 3x3 ----
    if (tid < 9) sW[tid] = make_float2(fw3[ch0 * 9 + tid], fw3[ch0 * 9 + 9 + tid]);
    __syncthreads();
    stage2<3>(sA, sB, sW, r, cs);
#pragma unroll
    for (int f = 0; f < 4; f++) {
        float4 gv = *(const float4*)(gbase + r * 64 + cs + f * 4);
        const float2* sp = &sB[(r + 3) * PST + cs + 3 + f * 4];
        fma2(accAll[f * 4 + 0], *(const unsigned long long*)&sp[0], pk2(gv.x, gv.x));
        fma2(accAll[f * 4 + 1], *(const unsigned long long*)&sp[1], pk2(gv.y, gv.y));
        fma2(accAll[f * 4 + 2], *(const unsigned long long*)&sp[2], pk2(gv.z, gv.z));
        fma2(accAll[f * 4 + 3], *(const unsigned long long*)&sp[3], pk2(gv.w, gv.w));
    }
    __syncthreads();
    // ---- 5x5 ----
    if (tid < 25) sW[tid] = make_float2(fw5[ch0 * 25 + tid], fw5[ch0 * 25 + 25 + tid]);
    __syncthreads();
    stage2<5>(sB, sA, sW, r, cs);
#pragma unroll
    for (int f = 0; f < 4; f++) {
        float4 gv = *(const float4*)(gbase + HW + r * 64 + cs + f * 4);
        const float2* sp = &sA[(r + 3) * PST + cs + 3 + f * 4];
        fma2(accAll[f * 4 + 0], *(const unsigned long long*)&sp[0], pk2(gv.x, gv.x));
        fma2(accAll[f * 4 + 1], *(const unsigned long long*)&sp[1], pk2(gv.y, gv.y));
        fma2(accAll[f * 4 + 2], *(const unsigned long long*)&sp[2], pk2(gv.z, gv.z));
        fma2(accAll[f * 4 + 3], *(const unsigned long long*)&sp[3], pk2(gv.w, gv.w));
    }
    __syncthreads();
    // ---- 7x7 ----
    if (tid < 49) sW[tid] = make_float2(fw7[ch0 * 49 + tid], fw7[ch0 * 49 + 49 + tid]);
    __syncthreads();
    stage2<7>(sA, sB, sW, r, cs);
    float ls0 = 0.f, ls1 = 0.f;
#pragma unroll
    for (int f = 0; f < 4; f++) {
        float4 gv = *(const float4*)(gbase + 2 * HW + r * 64 + cs + f * 4);
        const float2* sp = &sB[(r + 3) * PST + cs + 3 + f * 4];
        float g4[4] = {gv.x, gv.y, gv.z, gv.w};
#pragma unroll
        for (int j = 0; j < 4; j++) {
            unsigned long long v = *(const unsigned long long*)&sp[j];
            fma2(accAll[f * 4 + j], v, pk2(g4[j], g4[j]));
            float lo, hi;
            upk2(v, lo, hi);
            ls0 += lo;
            ls1 += hi;
        }
    }
    for (int off = 16; off; off >>= 1) {
        ls0 += __shfl_xor_sync(0xffffffffu, ls0, off);
        ls1 += __shfl_xor_sync(0xffffffffu, ls1, off);
    }
    if (lane == 0) sRed[wrp] = make_float2(ls0, ls1);
    __syncthreads();
    float t0 = 0.f, t1 = 0.f;
#pragma unroll
    for (int i = 0; i < 8; i++) { t0 += sRed[i].x; t1 += sRed[i].y; }
    const unsigned long long mean2 = pk2(t0 * (1.f / 4096.f), t1 * (1.f / 4096.f));

    float* d0 = &g_ctxall[((size_t)(b * C + ch0) << 12) + r * 64 + cs];
    float* d1 = d0 + HW;
#pragma unroll
    for (int f = 0; f < 4; f++) {
        float4 gv = *(const float4*)(gbase + 3 * HW + r * 64 + cs + f * 4);
        float g4[4] = {gv.x, gv.y, gv.z, gv.w};
        float4 o0, o1;
        float* po0 = &o0.x;
        float* po1 = &o1.x;
#pragma unroll
        for (int j = 0; j < 4; j++) {
            unsigned long long a = accAll[f * 4 + j];
            fma2(a, mean2, pk2(g4[j], g4[j]));
            upk2(a, po0[j], po1[j]);
        }
        *(float4*)&d0[f * 4] = o0;
        *(float4*)&d1[f * 4] = o1;
    }
}

// =====================================================================
// K3: key logits (float4 vectorized)
// =====================================================================
__global__ __launch_bounds__(256) void k_keylogit(const float* __restrict__ key_w,
                                                  const float* __restrict__ key_b) {
    __shared__ float kw[C];
    const int tid = threadIdx.x;
    kw[tid] = key_w[tid];
    __syncthreads();
    const int b  = blockIdx.x >> 2;
    const int i4 = ((blockIdx.x & 3) << 8) + tid;    // float4 index 0..1023
    const float4* p = (const float4*)&g_ctxall[(size_t)(b * C) << 12] + i4;
    float kb = key_b[0];
    float4 acc = {kb, kb, kb, kb};
#pragma unroll 8
    for (int c = 0; c < C; c++) {
        float4 xv = p[c << 10];                      // plane stride = 1024 float4
        float w = kw[c];
        acc.x += w * xv.x; acc.y += w * xv.y;
        acc.z += w * xv.z; acc.w += w * xv.w;
    }
    ((float4*)&g_klog[b << 12])[i4] = acc;
}

// =====================================================================
// K4: softmax over HW per batch
// =====================================================================
__global__ __launch_bounds__(256) void k_softmax() {
    __shared__ float red[8];
    const int b = blockIdx.x, tid = threadIdx.x;
    const float* p = &g_klog[b << 12];
    float v[16];
    float m = -1e30f;
#pragma unroll
    for (int i = 0; i < 16; i++) { v[i] = p[tid + (i << 8)]; m = fmaxf(m, v[i]); }
    for (int off = 16; off; off >>= 1) m = fmaxf(m, __shfl_xor_sync(0xffffffffu, m, off));
    if ((tid & 31) == 0) red[tid >> 5] = m;
    __syncthreads();
    float bm = red[0];
#pragma unroll
    for (int i = 1; i < 8; i++) bm = fmaxf(bm, red[i]);
    __syncthreads();
    float s = 0.f;
#pragma unroll
    for (int i = 0; i < 16; i++) { v[i] = expf(v[i] - bm); s += v[i]; }
    for (int off = 16; off; off >>= 1) s += __shfl_xor_sync(0xffffffffu, s, off);
    if ((tid & 31) == 0) red[tid >> 5] = s;
    __syncthreads();
    float tot = 0.f;
#pragma unroll
    for (int i = 0; i < 8; i++) tot += red[i];
    const float inv = 1.f / tot;
    float* o = &g_k[b << 12];
#pragma unroll
    for (int i = 0; i < 16; i++) o[tid + (i << 8)] = v[i] * inv;
}

// =====================================================================
// K5: qk[b,c] = sum_n ctx_all[b,c,n] * k[b,n]  (float4 vectorized)
// =====================================================================
__global__ __launch_bounds__(256) void k_qk() {
    __shared__ float sRed[8];
    const int tid = threadIdx.x;
    const int bc = blockIdx.x;
    const float4* p  = (const float4*)&g_ctxall[(size_t)bc << 12];
    const float4* kp = (const float4*)&g_k[(bc >> 8) << 12];
    float acc = 0.f;
#pragma unroll
    for (int i = 0; i < 4; i++) {
        int n = tid + (i << 8);
        float4 a = p[n], k4 = kp[n];
        acc += a.x * k4.x + a.y * k4.y + a.z * k4.z + a.w * k4.w;
    }
    for (int off = 16; off; off >>= 1) acc += __shfl_xor_sync(0xffffffffu, acc, off);
    if ((tid & 31) == 0) sRed[tid >> 5] = acc;
    __syncthreads();
    if (tid == 0) {
        float t = 0.f;
#pragma unroll
        for (int i = 0; i < 8; i++) t += sRed[i];
        g_qk[bc] = t;
    }
}

// =====================================================================
// K6: v = v2( relu( LN( v1(qk) ) ) )
// =====================================================================
__global__ __launch_bounds__(256) void k_vmlp(const float* __restrict__ v1_w,
                                              const float* __restrict__ v1_b,
                                              const float* __restrict__ ln_w,
                                              const float* __restrict__ ln_b,
                                              const float* __restrict__ v2_w,
                                              const float* __restrict__ v2_b) {
    __shared__ float sqk[B * C];
    __shared__ float sv[B * 16];
    const int tid = threadIdx.x;
    for (int i = tid; i < B * C; i += 256) sqk[i] = g_qk[i];
    __syncthreads();
    const int b = tid >> 4, j = tid & 15;
    float acc = v1_b[j];
#pragma unroll 4
    for (int c = 0; c < C; c++) acc += v1_w[j * C + c] * sqk[b * C + c];
    float mu = acc;
    for (int off = 8; off; off >>= 1) mu += __shfl_xor_sync(0xffffffffu, mu, off);
    mu *= (1.f / 16.f);
    float d = acc - mu;
    float var = d * d;
    for (int off = 8; off; off >>= 1) var += __shfl_xor_sync(0xffffffffu, var, off);
    var *= (1.f / 16.f);
    float vn = d * rsqrtf(var + 1e-5f);
    vn = vn * ln_w[j] + ln_b[j];
    vn = fmaxf(vn, 0.f);
    sv[tid] = vn;
    __syncthreads();
    const int b2 = tid >> 4;
    const int jo = tid & 15;
#pragma unroll
    for (int i = 0; i < 16; i++) {
        int co = jo + (i << 4);
        float a = v2_b[co];
#pragma unroll
        for (int jj = 0; jj < 16; jj++) a += v2_w[co * 16 + jj] * sv[b2 * 16 + jj];
        g_v[b2 * C + co] = a;
    }
}

// =====================================================================
// K7: out = ctx_all + v (broadcast over H,W)
// =====================================================================
__global__ __launch_bounds__(256) void k_final(float* __restrict__ out) {
    const int idx4 = blockIdx.x * 256 + threadIdx.x;
    const size_t base = (size_t)idx4 << 2;
    const int bc = (int)(base >> 12);
    const float vv = g_v[bc];
    float4 t = *(const float4*)&g_ctxall[base];
    t.x += vv; t.y += vv; t.z += vv; t.w += vv;
    *(float4*)&out[base] = t;
}

// =====================================================================
extern "C" void kernel_launch(void* const* d_in, const int* in_sizes, int n_in,
                              void* d_out, int out_size) {
    const float* x      = (const float*)d_in[0];
    const float* conv_w = (const float*)d_in[1];
    const float* conv_b = (const float*)d_in[2];
    const float* fw3    = (const float*)d_in[3];
    const float* fw5    = (const float*)d_in[4];
    const float* fw7    = (const float*)d_in[5];
    const float* key_w  = (const float*)d_in[6];
    const float* key_b  = (const float*)d_in[7];
    const float* v1_w   = (const float*)d_in[8];
    const float* v1_b   = (const float*)d_in[9];
    const float* ln_w   = (const float*)d_in[10];
    const float* ln_b   = (const float*)d_in[11];
    const float* v2_w   = (const float*)d_in[12];
    const float* v2_b   = (const float*)d_in[13];

    static bool attr_set = false;
    if (!attr_set) {
        cudaFuncSetAttribute(k_gemm, cudaFuncAttributeMaxDynamicSharedMemorySize, GEMM_SMEM);
        cudaFuncSetAttribute(k_dwchain, cudaFuncAttributeMaxDynamicSharedMemorySize, DW_SMEM);
        attr_set = true;
    }

    k_wsplit<<<256, 256>>>(conv_w);
    k_gemm<<<1024, 256, GEMM_SMEM>>>(x);
    k_gates<<<1024, 256>>>(x, conv_w, conv_b);
    k_dwchain<<<2048, 256, DW_SMEM>>>(fw3, fw5, fw7, conv_b);
    k_keylogit<<<64, 256>>>(key_w, key_b);
    k_softmax<<<16, 256>>>();
    k_qk<<<4096, 256>>>();
    k_vmlp<<<1, 256>>>(v1_w, v1_b, ln_w, ln_b, v2_w, v2_b);
    k_final<<<16384, 256>>>((float*)d_out);
}

// round 8
// speedup vs baseline: 1.0018x; 1.0018x over previous
#include <cuda_runtime.h>
#include <cuda_bf16.h>
#include <mma.h>
#include <math.h>
#include <stdint.h>

using namespace nvcuda;

#define HW   4096
#define WD   64
#define C    256
#define B    16
#define NO   260   // 256 ctx channels + 4 gate channels

// ---------------- scratch (static device globals; no allocs) ----------------
__device__ float g_t[B * NO * HW];       // conv1x1 output: ctx(256, no bias) + gates(4, biased)
__device__ float g_ctxall[B * C * HW];   // ctx_all
__device__ float g_klog[B * HW];
__device__ float g_k[B * HW];
__device__ float g_qk[B * C];
__device__ float g_v[B * C];
__device__ __align__(16) __nv_bfloat16 g_wh[C * C];      // w hi split (ctx rows)
__device__ __align__(16) __nv_bfloat16 g_wl[C * C];      // w lo split

// ---------------- f32x2 helpers ---------------------------------------------
__device__ __forceinline__ unsigned long long pk2(float lo, float hi) {
    unsigned long long r;
    asm("mov.b64 %0,{%1,%2};" : "=l"(r) : "f"(lo), "f"(hi));
    return r;
}
__device__ __forceinline__ void upk2(unsigned long long v, float& lo, float& hi) {
    asm("mov.b64 {%0,%1},%2;" : "=f"(lo), "=f"(hi) : "l"(v));
}
__device__ __forceinline__ void fma2(unsigned long long& d, unsigned long long a,
                                     unsigned long long b) {
    asm("fma.rn.f32x2 %0,%1,%2,%0;" : "+l"(d) : "l"(a), "l"(b));
}

// ---------------- cp.async helpers -----------------------------------------
__device__ __forceinline__ unsigned s2u(const void* p) {
    return (unsigned)__cvta_generic_to_shared(p);
}
__device__ __forceinline__ void cp16(unsigned dst, const void* src) {
    asm volatile("cp.async.ca.shared.global [%0], [%1], 16;" :: "r"(dst), "l"(src));
}
#define CP_COMMIT() asm volatile("cp.async.commit_group;")
#define CP_WAIT1()  asm volatile("cp.async.wait_group 1;")

// =====================================================================
// K0: split w (ctx rows 0..255) into bf16 hi/lo
// =====================================================================
__global__ __launch_bounds__(256) void k_wsplit(const float* __restrict__ w) {
    int idx = blockIdx.x * 256 + threadIdx.x;
    float v = w[idx];
    __nv_bfloat16 h = __float2bfloat16(v);
    g_wh[idx] = h;
    g_wl[idx] = __float2bfloat16(v - __bfloat162float(h));
}

// =====================================================================
// K1: wmma bf16 GEMM (3-product hi/lo split), in-kernel x conversion.
// =====================================================================
#define BUF_ELEMS 18944
#define OFF_AL 5120
#define OFF_BH 10240
#define OFF_BL 14592
#define GEMM_SMEM (2 * BUF_ELEMS * 2)   // 75776 bytes

__global__ __launch_bounds__(256, 2) void k_gemm(const float* __restrict__ x) {
    extern __shared__ __align__(16) __nv_bfloat16 sm[];
    const int tid = threadIdx.x;
    const int wid = tid >> 5;
    const int bx = blockIdx.x;
    const int pw = bx & 31, oh = (bx >> 5) & 1, b = bx >> 6;
    const int px0 = pw << 7, o0 = oh << 7;
    const int wm = wid & 1, wn = wid >> 1;

    wmma::fragment<wmma::accumulator, 16, 16, 16, float> acc[4][2];
#pragma unroll
    for (int i = 0; i < 4; i++)
#pragma unroll
        for (int j = 0; j < 2; j++) wmma::fill_fragment(acc[i][j], 0.f);

    auto stageA = [&](int ci) {
        unsigned base = s2u(sm + (ci & 1) * BUF_ELEMS);
        const int k0 = ci << 5;
#pragma unroll
        for (int v = 0; v < 2; v++) {
            const __nv_bfloat16* wsrc = v ? g_wl : g_wh;
#pragma unroll
            for (int it = 0; it < 2; it++) {
                int idx = tid + it * 256;
                int o = idx >> 2, u = idx & 3;
                cp16(base + (unsigned)((v * OFF_AL + o * 40 + u * 8) * 2),
                     wsrc + (o0 + o) * 256 + k0 + u * 8);
            }
        }
    };
    auto ldx = [&](float4* R, int ci) {
        const int k0 = ci << 5;
#pragma unroll
        for (int it = 0; it < 4; it++) {
            int fi = it * 256 + tid;
            int k = fi >> 5, u = fi & 31;
            R[it] = *(const float4*)(x + (((size_t)(b * C + k0 + k)) << 12) + px0 + u * 4);
        }
    };
    auto stsB = [&](const float4* R, int buf) {
        __nv_bfloat16* bp = sm + buf * BUF_ELEMS;
#pragma unroll
        for (int it = 0; it < 4; it++) {
            int fi = it * 256 + tid;
            int k = fi >> 5, u = fi & 31;
            float4 v = R[it];
            __nv_bfloat16 h0 = __float2bfloat16(v.x), h1 = __float2bfloat16(v.y);
            __nv_bfloat16 h2 = __float2bfloat16(v.z), h3 = __float2bfloat16(v.w);
            __nv_bfloat162 hp0 = {h0, h1}, hp1 = {h2, h3};
            __nv_bfloat162 lp0 = {__float2bfloat16(v.x - __bfloat162float(h0)),
                                  __float2bfloat16(v.y - __bfloat162float(h1))};
            __nv_bfloat162 lp1 = {__float2bfloat16(v.z - __bfloat162float(h2)),
                                  __float2bfloat16(v.w - __bfloat162float(h3))};
            uint2 hv = {*(uint32_t*)&hp0, *(uint32_t*)&hp1};
            uint2 lv = {*(uint32_t*)&lp0, *(uint32_t*)&lp1};
            *(uint2*)(bp + OFF_BH + k * 136 + u * 4) = hv;
            *(uint2*)(bp + OFF_BL + k * 136 + u * 4) = lv;
        }
    };
    auto compute = [&](int ci) {
        const __nv_bfloat16* bufp = sm + (ci & 1) * BUF_ELEMS;
        const __nv_bfloat16* AH = bufp;
        const __nv_bfloat16* AL = bufp + OFF_AL;
        const __nv_bfloat16* BH = bufp + OFF_BH;
        const __nv_bfloat16* BL = bufp + OFF_BL;
#pragma unroll
        for (int kk = 0; kk < 2; kk++) {
            wmma::fragment<wmma::matrix_a, 16, 16, 16, __nv_bfloat16, wmma::row_major> af[4];
            wmma::fragment<wmma::matrix_b, 16, 16, 16, __nv_bfloat16, wmma::row_major> bhf[2], blf[2];
#pragma unroll
            for (int j = 0; j < 2; j++)
                wmma::load_matrix_sync(bhf[j], BH + kk * 16 * 136 + wn * 32 + j * 16, 136);
#pragma unroll
            for (int i = 0; i < 4; i++)
                wmma::load_matrix_sync(af[i], AH + (wm * 64 + i * 16) * 40 + kk * 16, 40);
#pragma unroll
            for (int i = 0; i < 4; i++)
#pragma unroll
                for (int j = 0; j < 2; j++)
                    wmma::mma_sync(acc[i][j], af[i], bhf[j], acc[i][j]);
#pragma unroll
            for (int j = 0; j < 2; j++)
                wmma::load_matrix_sync(blf[j], BL + kk * 16 * 136 + wn * 32 + j * 16, 136);
#pragma unroll
            for (int i = 0; i < 4; i++)
#pragma unroll
                for (int j = 0; j < 2; j++)
                    wmma::mma_sync(acc[i][j], af[i], blf[j], acc[i][j]);
#pragma unroll
            for (int i = 0; i < 4; i++)
                wmma::load_matrix_sync(af[i], AL + (wm * 64 + i * 16) * 40 + kk * 16, 40);
#pragma unroll
            for (int i = 0; i < 4; i++)
#pragma unroll
                for (int j = 0; j < 2; j++)
                    wmma::mma_sync(acc[i][j], af[i], bhf[j], acc[i][j]);
        }
    };

    float4 R[4];
    stageA(0);
    CP_COMMIT();
    ldx(R, 0);
    for (int ci = 0; ci < 8; ci++) {
        if (ci < 7) stageA(ci + 1);
        CP_COMMIT();
        CP_WAIT1();
        stsB(R, ci & 1);
        __syncthreads();
        if (ci < 7) ldx(R, ci + 1);
        compute(ci);
        __syncthreads();
    }
#pragma unroll
    for (int i = 0; i < 4; i++)
#pragma unroll
        for (int j = 0; j < 2; j++)
            wmma::store_matrix_sync(
                g_t + (((size_t)(b * NO + o0 + wm * 64 + i * 16)) << 12) + px0 + wn * 32 + j * 16,
                acc[i][j], HW, wmma::mem_row_major);
}

// =====================================================================
// K1b: gate outputs (o = 256..259), 4-way channel split
// =====================================================================
__global__ __launch_bounds__(256) void k_gates(const float* __restrict__ x,
                                               const float* __restrict__ w,
                                               const float* __restrict__ bias) {
    __shared__ float wg[C][4];
    __shared__ float red[4][4][64];
    const int tid = threadIdx.x;
    for (int i = tid; i < C * 4; i += 256) {
        int c = i >> 2, j = i & 3;
        wg[c][j] = w[(256 + j) * C + c];
    }
    __syncthreads();
    const int b   = blockIdx.x >> 6;
    const int px0 = (blockIdx.x & 63) << 6;
    const int pxi = tid & 63;
    const int q   = tid >> 6;
    const float* p = x + (((size_t)(b * C + q * 64)) << 12) + px0 + pxi;
    float a0 = 0.f, a1 = 0.f, a2 = 0.f, a3 = 0.f;
#pragma unroll 8
    for (int c = 0; c < 64; c++) {
        float xv = p[(size_t)c << 12];
        a0 += xv * wg[q * 64 + c][0];
        a1 += xv * wg[q * 64 + c][1];
        a2 += xv * wg[q * 64 + c][2];
        a3 += xv * wg[q * 64 + c][3];
    }
    red[q][0][pxi] = a0;
    red[q][1][pxi] = a1;
    red[q][2][pxi] = a2;
    red[q][3][pxi] = a3;
    __syncthreads();
    if (q == 0) {
#pragma unroll
        for (int j = 0; j < 4; j++) {
            float s = red[0][j][pxi] + red[1][j][pxi] + red[2][j][pxi] + red[3][j][pxi]
                      + bias[256 + j];
            g_t[(((size_t)(b * NO + 256 + j)) << 12) + px0 + pxi] = s;
        }
    }
}

// =====================================================================
// K2: dw3->gelu -> dw5->gelu -> dw7->gelu chain, 2 CHANNELS PER CTA via
// f32x2 (float2-interleaved planes). Lane map lr=lane&15, lc=lane>>4 ->
// conflict-free LDS.64 with PST=71. Dynamic smem 79.5KB, 2 CTA/SM.
// =====================================================================
__device__ __forceinline__ float gelu_exact(float v) {
    return 0.5f * v * (1.f + erff(v * 0.70710678118654752440f));
}

#define PST 71
#define PLANE2 (70 * PST)        // 4970 float2 per buffer
#define DW_SMEM (2 * PLANE2 * 8) // 79520 bytes

template <int KS>
__device__ __forceinline__ void stage2(const float2* __restrict__ s_in,
                                       float2* __restrict__ s_out,
                                       const float2* __restrict__ sW,
                                       int r, int cs) {
    const int P = KS / 2;
    unsigned long long acc[16];
#pragma unroll
    for (int i = 0; i < 16; i++) acc[i] = 0ull;
#pragma unroll
    for (int dy = 0; dy < KS; dy++) {
        unsigned long long row[16 + 2 * (KS / 2)];
        const float2* rp = &s_in[(r + 3 + dy - P) * PST + (cs + 3 - P)];
#pragma unroll
        for (int i = 0; i < 16 + 2 * P; i++) row[i] = *(const unsigned long long*)&rp[i];
#pragma unroll
        for (int dx = 0; dx < KS; dx++) {
            unsigned long long wv = *(const unsigned long long*)&sW[dy * KS + dx];
#pragma unroll
            for (int i = 0; i < 16; i++) fma2(acc[i], row[i + dx], wv);
        }
    }
    float2* op = &s_out[(r + 3) * PST + cs + 3];
#pragma unroll
    for (int i = 0; i < 16; i++) {
        float lo, hi;
        upk2(acc[i], lo, hi);
        op[i] = make_float2(gelu_exact(lo), gelu_exact(hi));
    }
}

__global__ __launch_bounds__(256) void k_dwchain(const float* __restrict__ fw3,
                                                 const float* __restrict__ fw5,
                                                 const float* __restrict__ fw7,
                                                 const float* __restrict__ cb) {
    extern __shared__ __align__(16) float2 dsm[];
    float2* sA = dsm;
    float2* sB = dsm + PLANE2;
    __shared__ float2 sW[49];
    __shared__ float2 sRed[8];
    const int tid = threadIdx.x;
    const int b   = blockIdx.x >> 7;
    const int ch0 = (blockIdx.x & 127) << 1;
    const int wrp  = tid >> 5;
    const int lane = tid & 31;
    const int lr = lane & 15, lc = lane >> 4;
    const int r  = (wrp & 3) * 16 + lr;              // 0..63
    const int cs = (((wrp >> 2) << 1) + lc) << 4;    // 0,16,32,48

    for (int i = tid; i < 2 * PLANE2; i += 256) dsm[i] = make_float2(0.f, 0.f);
    __syncthreads();

    const float bv0 = cb[ch0], bv1 = cb[ch0 + 1];
    const float* s0 = &g_t[(size_t)(b * NO + ch0) << 12];
    const float* s1 = s0 + HW;
#pragma unroll
    for (int i = 0; i < 4; i++) {
        int idx4 = tid + i * 256;                    // 0..1023
        int rr = idx4 >> 4;
        int c4 = (idx4 & 15) << 2;
        float4 a = *(const float4*)(s0 + rr * 64 + c4);
        float4 bb = *(const float4*)(s1 + rr * 64 + c4);
        float2* dst = &sA[(rr + 3) * PST + c4 + 3];
        dst[0] = make_float2(a.x + bv0, bb.x + bv1);
        dst[1] = make_float2(a.y + bv0, bb.y + bv1);
        dst[2] = make_float2(a.z + bv0, bb.z + bv1);
        dst[3] = make_float2(a.w + bv0, bb.w + bv1);
    }

    const float* gbase = &g_t[(size_t)(b * NO + C) << 12];
    unsigned long long accAll[16];
#pragma unroll
    for (int i = 0; i < 16; i++) accAll[i] = 0ull;

    // ---- 3x3 ----
    if (tid < 9) sW[tid] = make_float2(fw3[ch0 * 9 + tid], fw3[ch0 * 9 + 9 + tid]);
    __syncthreads();
    stage2<3>(sA, sB, sW, r, cs);
#pragma unroll
    for (int f = 0; f < 4; f++) {
        float4 gv = *(const float4*)(gbase + r * 64 + cs + f * 4);
        const float2* sp = &sB[(r + 3) * PST + cs + 3 + f * 4];
        fma2(accAll[f * 4 + 0], *(const unsigned long long*)&sp[0], pk2(gv.x, gv.x));
        fma2(accAll[f * 4 + 1], *(const unsigned long long*)&sp[1], pk2(gv.y, gv.y));
        fma2(accAll[f * 4 + 2], *(const unsigned long long*)&sp[2], pk2(gv.z, gv.z));
        fma2(accAll[f * 4 + 3], *(const unsigned long long*)&sp[3], pk2(gv.w, gv.w));
    }
    __syncthreads();
    // ---- 5x5 ----
    if (tid < 25) sW[tid] = make_float2(fw5[ch0 * 25 + tid], fw5[ch0 * 25 + 25 + tid]);
    __syncthreads();
    stage2<5>(sB, sA, sW, r, cs);
#pragma unroll
    for (int f = 0; f < 4; f++) {
        float4 gv = *(const float4*)(gbase + HW + r * 64 + cs + f * 4);
        const float2* sp = &sA[(r + 3) * PST + cs + 3 + f * 4];
        fma2(accAll[f * 4 + 0], *(const unsigned long long*)&sp[0], pk2(gv.x, gv.x));
        fma2(accAll[f * 4 + 1], *(const unsigned long long*)&sp[1], pk2(gv.y, gv.y));
        fma2(accAll[f * 4 + 2], *(const unsigned long long*)&sp[2], pk2(gv.z, gv.z));
        fma2(accAll[f * 4 + 3], *(const unsigned long long*)&sp[3], pk2(gv.w, gv.w));
    }
    __syncthreads();
    // ---- 7x7 ----
    if (tid < 49) sW[tid] = make_float2(fw7[ch0 * 49 + tid], fw7[ch0 * 49 + 49 + tid]);
    __syncthreads();
    stage2<7>(sA, sB, sW, r, cs);
    float ls0 = 0.f, ls1 = 0.f;
#pragma unroll
    for (int f = 0; f < 4; f++) {
        float4 gv = *(const float4*)(gbase + 2 * HW + r * 64 + cs + f * 4);
        const float2* sp = &sB[(r + 3) * PST + cs + 3 + f * 4];
        float g4[4] = {gv.x, gv.y, gv.z, gv.w};
#pragma unroll
        for (int j = 0; j < 4; j++) {
            unsigned long long v = *(const unsigned long long*)&sp[j];
            fma2(accAll[f * 4 + j], v, pk2(g4[j], g4[j]));
            float lo, hi;
            upk2(v, lo, hi);
            ls0 += lo;
            ls1 += hi;
        }
    }
    for (int off = 16; off; off >>= 1) {
        ls0 += __shfl_xor_sync(0xffffffffu, ls0, off);
        ls1 += __shfl_xor_sync(0xffffffffu, ls1, off);
    }
    if (lane == 0) sRed[wrp] = make_float2(ls0, ls1);
    __syncthreads();
    float t0 = 0.f, t1 = 0.f;
#pragma unroll
    for (int i = 0; i < 8; i++) { t0 += sRed[i].x; t1 += sRed[i].y; }
    const unsigned long long mean2 = pk2(t0 * (1.f / 4096.f), t1 * (1.f / 4096.f));

    float* d0 = &g_ctxall[((size_t)(b * C + ch0) << 12) + r * 64 + cs];
    float* d1 = d0 + HW;
#pragma unroll
    for (int f = 0; f < 4; f++) {
        float4 gv = *(const float4*)(gbase + 3 * HW + r * 64 + cs + f * 4);
        float g4[4] = {gv.x, gv.y, gv.z, gv.w};
        float4 o0, o1;
        float* po0 = &o0.x;
        float* po1 = &o1.x;
#pragma unroll
        for (int j = 0; j < 4; j++) {
            unsigned long long a = accAll[f * 4 + j];
            fma2(a, mean2, pk2(g4[j], g4[j]));
            upk2(a, po0[j], po1[j]);
        }
        *(float4*)&d0[f * 4] = o0;
        *(float4*)&d1[f * 4] = o1;
    }
}

// =====================================================================
// K3: key logits (float4 vectorized)
// =====================================================================
__global__ __launch_bounds__(256) void k_keylogit(const float* __restrict__ key_w,
                                                  const float* __restrict__ key_b) {
    __shared__ float kw[C];
    const int tid = threadIdx.x;
    kw[tid] = key_w[tid];
    __syncthreads();
    const int b  = blockIdx.x >> 2;
    const int i4 = ((blockIdx.x & 3) << 8) + tid;    // float4 index 0..1023
    const float4* p = (const float4*)&g_ctxall[(size_t)(b * C) << 12] + i4;
    float kb = key_b[0];
    float4 acc = {kb, kb, kb, kb};
#pragma unroll 8
    for (int c = 0; c < C; c++) {
        float4 xv = p[c << 10];                      // plane stride = 1024 float4
        float w = kw[c];
        acc.x += w * xv.x; acc.y += w * xv.y;
        acc.z += w * xv.z; acc.w += w * xv.w;
    }
    ((float4*)&g_klog[b << 12])[i4] = acc;
}

// =====================================================================
// K4: softmax over HW per batch
// =====================================================================
__global__ __launch_bounds__(256) void k_softmax() {
    __shared__ float red[8];
    const int b = blockIdx.x, tid = threadIdx.x;
    const float* p = &g_klog[b << 12];
    float v[16];
    float m = -1e30f;
#pragma unroll
    for (int i = 0; i < 16; i++) { v[i] = p[tid + (i << 8)]; m = fmaxf(m, v[i]); }
    for (int off = 16; off; off >>= 1) m = fmaxf(m, __shfl_xor_sync(0xffffffffu, m, off));
    if ((tid & 31) == 0) red[tid >> 5] = m;
    __syncthreads();
    float bm = red[0];
#pragma unroll
    for (int i = 1; i < 8; i++) bm = fmaxf(bm, red[i]);
    __syncthreads();
    float s = 0.f;
#pragma unroll
    for (int i = 0; i < 16; i++) { v[i] = expf(v[i] - bm); s += v[i]; }
    for (int off = 16; off; off >>= 1) s += __shfl_xor_sync(0xffffffffu, s, off);
    if ((tid & 31) == 0) red[tid >> 5] = s;
    __syncthreads();
    float tot = 0.f;
#pragma unroll
    for (int i = 0; i < 8; i++) tot += red[i];
    const float inv = 1.f / tot;
    float* o = &g_k[b << 12];
#pragma unroll
    for (int i = 0; i < 16; i++) o[tid + (i << 8)] = v[i] * inv;
}

// =====================================================================
// K5: qk[b,c] = sum_n ctx_all[b,c,n] * k[b,n]  (float4 vectorized)
// =====================================================================
__global__ __launch_bounds__(256) void k_qk() {
    __shared__ float sRed[8];
    const int tid = threadIdx.x;
    const int bc = blockIdx.x;
    const float4* p  = (const float4*)&g_ctxall[(size_t)bc << 12];
    const float4* kp = (const float4*)&g_k[(bc >> 8) << 12];
    float acc = 0.f;
#pragma unroll
    for (int i = 0; i < 4; i++) {
        int n = tid + (i << 8);
        float4 a = p[n], k4 = kp[n];
        acc += a.x * k4.x + a.y * k4.y + a.z * k4.z + a.w * k4.w;
    }
    for (int off = 16; off; off >>= 1) acc += __shfl_xor_sync(0xffffffffu, acc, off);
    if ((tid & 31) == 0) sRed[tid >> 5] = acc;
    __syncthreads();
    if (tid == 0) {
        float t = 0.f;
#pragma unroll
        for (int i = 0; i < 8; i++) t += sRed[i];
        g_qk[bc] = t;
    }
}

// =====================================================================
// K6: v = v2( relu( LN( v1(qk) ) ) )
// =====================================================================
__global__ __launch_bounds__(256) void k_vmlp(const float* __restrict__ v1_w,
                                              const float* __restrict__ v1_b,
                                              const float* __restrict__ ln_w,
                                              const float* __restrict__ ln_b,
                                              const float* __restrict__ v2_w,
                                              const float* __restrict__ v2_b) {
    __shared__ float sqk[B * C];
    __shared__ float sv[B * 16];
    const int tid = threadIdx.x;
    for (int i = tid; i < B * C; i += 256) sqk[i] = g_qk[i];
    __syncthreads();
    const int b = tid >> 4, j = tid & 15;
    float acc = v1_b[j];
#pragma unroll 4
    for (int c = 0; c < C; c++) acc += v1_w[j * C + c] * sqk[b * C + c];
    float mu = acc;
    for (int off = 8; off; off >>= 1) mu += __shfl_xor_sync(0xffffffffu, mu, off);
    mu *= (1.f / 16.f);
    float d = acc - mu;
    float var = d * d;
    for (int off = 8; off; off >>= 1) var += __shfl_xor_sync(0xffffffffu, var, off);
    var *= (1.f / 16.f);
    float vn = d * rsqrtf(var + 1e-5f);
    vn = vn * ln_w[j] + ln_b[j];
    vn = fmaxf(vn, 0.f);
    sv[tid] = vn;
    __syncthreads();
    const int b2 = tid >> 4;
    const int jo = tid & 15;
#pragma unroll
    for (int i = 0; i < 16; i++) {
        int co = jo + (i << 4);
        float a = v2_b[co];
#pragma unroll
        for (int jj = 0; jj < 16; jj++) a += v2_w[co * 16 + jj] * sv[b2 * 16 + jj];
        g_v[b2 * C + co] = a;
    }
}

// =====================================================================
// K7: out = ctx_all + v (broadcast over H,W)
// =====================================================================
__global__ __launch_bounds__(256) void k_final(float* __restrict__ out) {
    const int idx4 = blockIdx.x * 256 + threadIdx.x;
    const size_t base = (size_t)idx4 << 2;
    const int bc = (int)(base >> 12);
    const float vv = g_v[bc];
    float4 t = *(const float4*)&g_ctxall[base];
    t.x += vv; t.y += vv; t.z += vv; t.w += vv;
    *(float4*)&out[base] = t;
}

// =====================================================================
extern "C" void kernel_launch(void* const* d_in, const int* in_sizes, int n_in,
                              void* d_out, int out_size) {
    const float* x      = (const float*)d_in[0];
    const float* conv_w = (const float*)d_in[1];
    const float* conv_b = (const float*)d_in[2];
    const float* fw3    = (const float*)d_in[3];
    const float* fw5    = (const float*)d_in[4];
    const float* fw7    = (const float*)d_in[5];
    const float* key_w  = (const float*)d_in[6];
    const float* key_b  = (const float*)d_in[7];
    const float* v1_w   = (const float*)d_in[8];
    const float* v1_b   = (const float*)d_in[9];
    const float* ln_w   = (const float*)d_in[10];
    const float* ln_b   = (const float*)d_in[11];
    const float* v2_w   = (const float*)d_in[12];
    const float* v2_b   = (const float*)d_in[13];

    static bool attr_set = false;
    if (!attr_set) {
        cudaFuncSetAttribute(k_gemm, cudaFuncAttributeMaxDynamicSharedMemorySize, GEMM_SMEM);
        cudaFuncSetAttribute(k_dwchain, cudaFuncAttributeMaxDynamicSharedMemorySize, DW_SMEM);
        attr_set = true;
    }

    k_wsplit<<<256, 256>>>(conv_w);
    k_gemm<<<1024, 256, GEMM_SMEM>>>(x);
    k_gates<<<1024, 256>>>(x, conv_w, conv_b);
    k_dwchain<<<2048, 256, DW_SMEM>>>(fw3, fw5, fw7, conv_b);
    k_keylogit<<<64, 256>>>(key_w, key_b);
    k_softmax<<<16, 256>>>();
    k_qk<<<4096, 256>>>();
    k_vmlp<<<1, 256>>>(v1_w, v1_b, ln_w, ln_b, v2_w, v2_b);
    k_final<<<16384, 256>>>((float*)d_out);
}

// round 10
// speedup vs baseline: 1.0226x; 1.0208x over previous
#include <cuda_runtime.h>
#include <cuda_bf16.h>
#include <mma.h>
#include <math.h>
#include <stdint.h>

using namespace nvcuda;

#define HW   4096
#define WD   64
#define C    256
#define B    16
#define NO   260   // 256 ctx channels + 4 gate channels

// ---------------- scratch (static device globals; no allocs) ----------------
__device__ float g_t[B * NO * HW];       // conv1x1 output: ctx(256, no bias) + gates(4, biased)
__device__ float g_ctxall[B * C * HW];   // ctx_all
__device__ float g_klog[B * HW];
__device__ float g_k[B * HW];
__device__ float g_qk[B * C];
__device__ float g_v[B * C];
__device__ __align__(16) __nv_bfloat16 g_wh[C * C];      // w hi split (ctx rows)
__device__ __align__(16) __nv_bfloat16 g_wl[C * C];      // w lo split

// ---------------- cp.async helpers -----------------------------------------
__device__ __forceinline__ unsigned s2u(const void* p) {
    return (unsigned)__cvta_generic_to_shared(p);
}
__device__ __forceinline__ void cp16(unsigned dst, const void* src) {
    asm volatile("cp.async.ca.shared.global [%0], [%1], 16;" :: "r"(dst), "l"(src));
}
#define CP_COMMIT() asm volatile("cp.async.commit_group;")
#define CP_WAIT1()  asm volatile("cp.async.wait_group 1;")

// =====================================================================
// K0: split w (ctx rows 0..255) into bf16 hi/lo
// =====================================================================
__global__ __launch_bounds__(256) void k_wsplit(const float* __restrict__ w) {
    int idx = blockIdx.x * 256 + threadIdx.x;
    float v = w[idx];
    __nv_bfloat16 h = __float2bfloat16(v);
    g_wh[idx] = h;
    g_wl[idx] = __float2bfloat16(v - __bfloat162float(h));
}

// =====================================================================
// K1: wmma bf16 GEMM (3-product hi/lo split), in-kernel x conversion.
// =====================================================================
#define BUF_ELEMS 18944
#define OFF_AL 5120
#define OFF_BH 10240
#define OFF_BL 14592
#define GEMM_SMEM (2 * BUF_ELEMS * 2)   // 75776 bytes

__global__ __launch_bounds__(256, 2) void k_gemm(const float* __restrict__ x) {
    extern __shared__ __align__(16) __nv_bfloat16 sm[];
    const int tid = threadIdx.x;
    const int wid = tid >> 5;
    const int bx = blockIdx.x;
    const int pw = bx & 31, oh = (bx >> 5) & 1, b = bx >> 6;
    const int px0 = pw << 7, o0 = oh << 7;
    const int wm = wid & 1, wn = wid >> 1;

    wmma::fragment<wmma::accumulator, 16, 16, 16, float> acc[4][2];
#pragma unroll
    for (int i = 0; i < 4; i++)
#pragma unroll
        for (int j = 0; j < 2; j++) wmma::fill_fragment(acc[i][j], 0.f);

    auto stageA = [&](int ci) {
        unsigned base = s2u(sm + (ci & 1) * BUF_ELEMS);
        const int k0 = ci << 5;
#pragma unroll
        for (int v = 0; v < 2; v++) {
            const __nv_bfloat16* wsrc = v ? g_wl : g_wh;
#pragma unroll
            for (int it = 0; it < 2; it++) {
                int idx = tid + it * 256;
                int o = idx >> 2, u = idx & 3;
                cp16(base + (unsigned)((v * OFF_AL + o * 40 + u * 8) * 2),
                     wsrc + (o0 + o) * 256 + k0 + u * 8);
            }
        }
    };
    auto ldx = [&](float4* R, int ci) {
        const int k0 = ci << 5;
#pragma unroll
        for (int it = 0; it < 4; it++) {
            int fi = it * 256 + tid;
            int k = fi >> 5, u = fi & 31;
            R[it] = *(const float4*)(x + (((size_t)(b * C + k0 + k)) << 12) + px0 + u * 4);
        }
    };
    auto stsB = [&](const float4* R, int buf) {
        __nv_bfloat16* bp = sm + buf * BUF_ELEMS;
#pragma unroll
        for (int it = 0; it < 4; it++) {
            int fi = it * 256 + tid;
            int k = fi >> 5, u = fi & 31;
            float4 v = R[it];
            __nv_bfloat16 h0 = __float2bfloat16(v.x), h1 = __float2bfloat16(v.y);
            __nv_bfloat16 h2 = __float2bfloat16(v.z), h3 = __float2bfloat16(v.w);
            __nv_bfloat162 hp0 = {h0, h1}, hp1 = {h2, h3};
            __nv_bfloat162 lp0 = {__float2bfloat16(v.x - __bfloat162float(h0)),
                                  __float2bfloat16(v.y - __bfloat162float(h1))};
            __nv_bfloat162 lp1 = {__float2bfloat16(v.z - __bfloat162float(h2)),
                                  __float2bfloat16(v.w - __bfloat162float(h3))};
            uint2 hv = {*(uint32_t*)&hp0, *(uint32_t*)&hp1};
            uint2 lv = {*(uint32_t*)&lp0, *(uint32_t*)&lp1};
            *(uint2*)(bp + OFF_BH + k * 136 + u * 4) = hv;
            *(uint2*)(bp + OFF_BL + k * 136 + u * 4) = lv;
        }
    };
    auto compute = [&](int ci) {
        const __nv_bfloat16* bufp = sm + (ci & 1) * BUF_ELEMS;
        const __nv_bfloat16* AH = bufp;
        const __nv_bfloat16* AL = bufp + OFF_AL;
        const __nv_bfloat16* BH = bufp + OFF_BH;
        const __nv_bfloat16* BL = bufp + OFF_BL;
#pragma unroll
        for (int kk = 0; kk < 2; kk++) {
            wmma::fragment<wmma::matrix_a, 16, 16, 16, __nv_bfloat16, wmma::row_major> af[4];
            wmma::fragment<wmma::matrix_b, 16, 16, 16, __nv_bfloat16, wmma::row_major> bhf[2], blf[2];
#pragma unroll
            for (int j = 0; j < 2; j++)
                wmma::load_matrix_sync(bhf[j], BH + kk * 16 * 136 + wn * 32 + j * 16, 136);
#pragma unroll
            for (int i = 0; i < 4; i++)
                wmma::load_matrix_sync(af[i], AH + (wm * 64 + i * 16) * 40 + kk * 16, 40);
#pragma unroll
            for (int i = 0; i < 4; i++)
#pragma unroll
                for (int j = 0; j < 2; j++)
                    wmma::mma_sync(acc[i][j], af[i], bhf[j], acc[i][j]);
#pragma unroll
            for (int j = 0; j < 2; j++)
                wmma::load_matrix_sync(blf[j], BL + kk * 16 * 136 + wn * 32 + j * 16, 136);
#pragma unroll
            for (int i = 0; i < 4; i++)
#pragma unroll
                for (int j = 0; j < 2; j++)
                    wmma::mma_sync(acc[i][j], af[i], blf[j], acc[i][j]);
#pragma unroll
            for (int i = 0; i < 4; i++)
                wmma::load_matrix_sync(af[i], AL + (wm * 64 + i * 16) * 40 + kk * 16, 40);
#pragma unroll
            for (int i = 0; i < 4; i++)
#pragma unroll
                for (int j = 0; j < 2; j++)
                    wmma::mma_sync(acc[i][j], af[i], bhf[j], acc[i][j]);
        }
    };

    float4 R[4];
    stageA(0);
    CP_COMMIT();
    ldx(R, 0);
    for (int ci = 0; ci < 8; ci++) {
        if (ci < 7) stageA(ci + 1);
        CP_COMMIT();
        CP_WAIT1();
        stsB(R, ci & 1);
        __syncthreads();
        if (ci < 7) ldx(R, ci + 1);
        compute(ci);
        __syncthreads();
    }
#pragma unroll
    for (int i = 0; i < 4; i++)
#pragma unroll
        for (int j = 0; j < 2; j++)
            wmma::store_matrix_sync(
                g_t + (((size_t)(b * NO + o0 + wm * 64 + i * 16)) << 12) + px0 + wn * 32 + j * 16,
                acc[i][j], HW, wmma::mem_row_major);
}

// =====================================================================
// K1b: gate outputs (o = 256..259), 4-way channel split
// =====================================================================
__global__ __launch_bounds__(256) void k_gates(const float* __restrict__ x,
                                               const float* __restrict__ w,
                                               const float* __restrict__ bias) {
    __shared__ float wg[C][4];
    __shared__ float red[4][4][64];
    const int tid = threadIdx.x;
    for (int i = tid; i < C * 4; i += 256) {
        int c = i >> 2, j = i & 3;
        wg[c][j] = w[(256 + j) * C + c];
    }
    __syncthreads();
    const int b   = blockIdx.x >> 6;
    const int px0 = (blockIdx.x & 63) << 6;
    const int pxi = tid & 63;
    const int q   = tid >> 6;
    const float* p = x + (((size_t)(b * C + q * 64)) << 12) + px0 + pxi;
    float a0 = 0.f, a1 = 0.f, a2 = 0.f, a3 = 0.f;
#pragma unroll 8
    for (int c = 0; c < 64; c++) {
        float xv = p[(size_t)c << 12];
        a0 += xv * wg[q * 64 + c][0];
        a1 += xv * wg[q * 64 + c][1];
        a2 += xv * wg[q * 64 + c][2];
        a3 += xv * wg[q * 64 + c][3];
    }
    red[q][0][pxi] = a0;
    red[q][1][pxi] = a1;
    red[q][2][pxi] = a2;
    red[q][3][pxi] = a3;
    __syncthreads();
    if (q == 0) {
#pragma unroll
        for (int j = 0; j < 4; j++) {
            float s = red[0][j][pxi] + red[1][j][pxi] + red[2][j][pxi] + red[3][j][pxi]
                      + bias[256 + j];
            g_t[(((size_t)(b * NO + 256 + j)) << 12) + px0 + pxi] = s;
        }
    }
}

// =====================================================================
// K2: dw3->gelu -> dw5->gelu -> dw7->gelu chain (R6 shape: 1 channel/CTA,
// 39.8KB static smem, 5 CTA/SM) with FAST branchless gelu
// (A&S 7.1.26 erf: rcp.approx + ex2.approx + imm-FFMA poly, |err|<=2e-7).
// =====================================================================
__device__ __forceinline__ float gelu_fast(float v) {
    float z  = v * 0.70710678118654752440f;
    float az = fabsf(z);
    float d  = fmaf(az, 0.3275911f, 1.0f);
    float t;  asm("rcp.approx.f32 %0,%1;" : "=f"(t) : "f"(d));
    float p  = fmaf(t, 1.061405429f, -1.453152027f);
    p = fmaf(p, t, 1.421413741f);
    p = fmaf(p, t, -0.284496736f);
    p = fmaf(p, t, 0.254829592f);
    p = p * t;
    float e;  asm("ex2.approx.f32 %0,%1;" : "=f"(e) : "f"(z * z * -1.442695040888963f));
    float er = fmaf(-p, e, 1.0f);            // erf(|z|)
    er = copysignf(er, z);
    return 0.5f * v * (1.0f + er);
}

#define PST 71

template <int KS>
__device__ __forceinline__ void stage_dw(const float* __restrict__ s_in,
                                         float* __restrict__ s_out,
                                         const float* __restrict__ sW,
                                         int r, int cs) {
    const int P = KS / 2;
    float acc[16];
#pragma unroll
    for (int i = 0; i < 16; i++) acc[i] = 0.f;
#pragma unroll
    for (int dy = 0; dy < KS; dy++) {
        float row[16 + 2 * (KS / 2)];
        const float* rp = &s_in[(r + 3 + dy - P) * PST + (cs + 3 - P)];
#pragma unroll
        for (int i = 0; i < 16 + 2 * P; i++) row[i] = rp[i];
#pragma unroll
        for (int dx = 0; dx < KS; dx++) {
            float wv = sW[dy * KS + dx];
#pragma unroll
            for (int i = 0; i < 16; i++) acc[i] += row[i + dx] * wv;
        }
    }
    float* op = &s_out[(r + 3) * PST + cs + 3];
#pragma unroll
    for (int i = 0; i < 16; i++) op[i] = gelu_fast(acc[i]);
}

__global__ __launch_bounds__(256) void k_dwchain(const float* __restrict__ fw3,
                                                 const float* __restrict__ fw5,
                                                 const float* __restrict__ fw7,
                                                 const float* __restrict__ cb) {
    __shared__ float sA[70 * PST];
    __shared__ float sB[70 * PST];
    __shared__ float sW[49];
    __shared__ float sRed[8];
    const int tid = threadIdx.x;
    const int b  = blockIdx.x >> 8;
    const int ch = blockIdx.x & 255;
    const int wrp  = tid >> 5;
    const int lane = tid & 31;
    const int lr = lane >> 1, lc = lane & 1;
    const int r  = (wrp & 3) * 16 + lr;
    const int cs = (((wrp >> 2) << 1) + lc) << 4;

    for (int i = tid; i < 70 * PST; i += 256) { sA[i] = 0.f; sB[i] = 0.f; }
    __syncthreads();

    const float bv = cb[ch];
    const float* src = &g_t[(size_t)(b * NO + ch) << 12];
#pragma unroll
    for (int i = 0; i < 16; i++) {
        int idx = tid + i * 256;
        int rr = idx >> 6, cc = idx & 63;
        sA[(rr + 3) * PST + cc + 3] = src[idx] + bv;
    }

    const float* gbase = &g_t[(size_t)(b * NO + C) << 12];
    float accAll[16];
#pragma unroll
    for (int i = 0; i < 16; i++) accAll[i] = 0.f;

    if (tid < 9) sW[tid] = fw3[ch * 9 + tid];
    __syncthreads();
    stage_dw<3>(sA, sB, sW, r, cs);
#pragma unroll
    for (int f = 0; f < 4; f++) {
        float4 gv = *(const float4*)(gbase + r * 64 + cs + f * 4);
        accAll[f * 4 + 0] += sB[(r + 3) * PST + cs + 3 + f * 4 + 0] * gv.x;
        accAll[f * 4 + 1] += sB[(r + 3) * PST + cs + 3 + f * 4 + 1] * gv.y;
        accAll[f * 4 + 2] += sB[(r + 3) * PST + cs + 3 + f * 4 + 2] * gv.z;
        accAll[f * 4 + 3] += sB[(r + 3) * PST + cs + 3 + f * 4 + 3] * gv.w;
    }
    __syncthreads();
    if (tid < 25) sW[tid] = fw5[ch * 25 + tid];
    __syncthreads();
    stage_dw<5>(sB, sA, sW, r, cs);
#pragma unroll
    for (int f = 0; f < 4; f++) {
        float4 gv = *(const float4*)(gbase + HW + r * 64 + cs + f * 4);
        accAll[f * 4 + 0] += sA[(r + 3) * PST + cs + 3 + f * 4 + 0] * gv.x;
        accAll[f * 4 + 1] += sA[(r + 3) * PST + cs + 3 + f * 4 + 1] * gv.y;
        accAll[f * 4 + 2] += sA[(r + 3) * PST + cs + 3 + f * 4 + 2] * gv.z;
        accAll[f * 4 + 3] += sA[(r + 3) * PST + cs + 3 + f * 4 + 3] * gv.w;
    }
    __syncthreads();
    if (tid < 49) sW[tid] = fw7[ch * 49 + tid];
    __syncthreads();
    stage_dw<7>(sA, sB, sW, r, cs);
    float lsum = 0.f;
#pragma unroll
    for (int f = 0; f < 4; f++) {
        float4 gv = *(const float4*)(gbase + 2 * HW + r * 64 + cs + f * 4);
        float v0 = sB[(r + 3) * PST + cs + 3 + f * 4 + 0];
        float v1 = sB[(r + 3) * PST + cs + 3 + f * 4 + 1];
        float v2 = sB[(r + 3) * PST + cs + 3 + f * 4 + 2];
        float v3 = sB[(r + 3) * PST + cs + 3 + f * 4 + 3];
        accAll[f * 4 + 0] += v0 * gv.x;
        accAll[f * 4 + 1] += v1 * gv.y;
        accAll[f * 4 + 2] += v2 * gv.z;
        accAll[f * 4 + 3] += v3 * gv.w;
        lsum += v0 + v1 + v2 + v3;
    }
    for (int off = 16; off; off >>= 1)
        lsum += __shfl_xor_sync(0xffffffffu, lsum, off);
    if ((tid & 31) == 0) sRed[tid >> 5] = lsum;
    __syncthreads();
    float tot = 0.f;
#pragma unroll
    for (int i = 0; i < 8; i++) tot += sRed[i];
    const float mean = tot * (1.f / 4096.f);

    float* dst = &g_ctxall[((size_t)(b * C + ch) << 12) + r * 64 + cs];
#pragma unroll
    for (int f = 0; f < 4; f++) {
        float4 gv = *(const float4*)(gbase + 3 * HW + r * 64 + cs + f * 4);
        float4 o;
        o.x = accAll[f * 4 + 0] + mean * gv.x;
        o.y = accAll[f * 4 + 1] + mean * gv.y;
        o.z = accAll[f * 4 + 2] + mean * gv.z;
        o.w = accAll[f * 4 + 3] + mean * gv.w;
        *(float4*)&dst[f * 4] = o;
    }
}

// =====================================================================
// K3: key logits (float4 vectorized)
// =====================================================================
__global__ __launch_bounds__(256) void k_keylogit(const float* __restrict__ key_w,
                                                  const float* __restrict__ key_b) {
    __shared__ float kw[C];
    const int tid = threadIdx.x;
    kw[tid] = key_w[tid];
    __syncthreads();
    const int b  = blockIdx.x >> 2;
    const int i4 = ((blockIdx.x & 3) << 8) + tid;    // float4 index 0..1023
    const float4* p = (const float4*)&g_ctxall[(size_t)(b * C) << 12] + i4;
    float kb = key_b[0];
    float4 acc = {kb, kb, kb, kb};
#pragma unroll 8
    for (int c = 0; c < C; c++) {
        float4 xv = p[c << 10];                      // plane stride = 1024 float4
        float w = kw[c];
        acc.x += w * xv.x; acc.y += w * xv.y;
        acc.z += w * xv.z; acc.w += w * xv.w;
    }
    ((float4*)&g_klog[b << 12])[i4] = acc;
}

// =====================================================================
// K4: softmax over HW per batch
// =====================================================================
__global__ __launch_bounds__(256) void k_softmax() {
    __shared__ float red[8];
    const int b = blockIdx.x, tid = threadIdx.x;
    const float* p = &g_klog[b << 12];
    float v[16];
    float m = -1e30f;
#pragma unroll
    for (int i = 0; i < 16; i++) { v[i] = p[tid + (i << 8)]; m = fmaxf(m, v[i]); }
    for (int off = 16; off; off >>= 1) m = fmaxf(m, __shfl_xor_sync(0xffffffffu, m, off));
    if ((tid & 31) == 0) red[tid >> 5] = m;
    __syncthreads();
    float bm = red[0];
#pragma unroll
    for (int i = 1; i < 8; i++) bm = fmaxf(bm, red[i]);
    __syncthreads();
    float s = 0.f;
#pragma unroll
    for (int i = 0; i < 16; i++) { v[i] = expf(v[i] - bm); s += v[i]; }
    for (int off = 16; off; off >>= 1) s += __shfl_xor_sync(0xffffffffu, s, off);
    if ((tid & 31) == 0) red[tid >> 5] = s;
    __syncthreads();
    float tot = 0.f;
#pragma unroll
    for (int i = 0; i < 8; i++) tot += red[i];
    const float inv = 1.f / tot;
    float* o = &g_k[b << 12];
#pragma unroll
    for (int i = 0; i < 16; i++) o[tid + (i << 8)] = v[i] * inv;
}

// =====================================================================
// K5: qk[b,c] = sum_n ctx_all[b,c,n] * k[b,n]  (float4 vectorized)
// =====================================================================
__global__ __launch_bounds__(256) void k_qk() {
    __shared__ float sRed[8];
    const int tid = threadIdx.x;
    const int bc = blockIdx.x;
    const float4* p  = (const float4*)&g_ctxall[(size_t)bc << 12];
    const float4* kp = (const float4*)&g_k[(bc >> 8) << 12];
    float acc = 0.f;
#pragma unroll
    for (int i = 0; i < 4; i++) {
        int n = tid + (i << 8);
        float4 a = p[n], k4 = kp[n];
        acc += a.x * k4.x + a.y * k4.y + a.z * k4.z + a.w * k4.w;
    }
    for (int off = 16; off; off >>= 1) acc += __shfl_xor_sync(0xffffffffu, acc, off);
    if ((tid & 31) == 0) sRed[tid >> 5] = acc;
    __syncthreads();
    if (tid == 0) {
        float t = 0.f;
#pragma unroll
        for (int i = 0; i < 8; i++) t += sRed[i];
        g_qk[bc] = t;
    }
}

// =====================================================================
// K6: v = v2( relu( LN( v1(qk) ) ) )
// =====================================================================
__global__ __launch_bounds__(256) void k_vmlp(const float* __restrict__ v1_w,
                                              const float* __restrict__ v1_b,
                                              const float* __restrict__ ln_w,
                                              const float* __restrict__ ln_b,
                                              const float* __restrict__ v2_w,
                                              const float* __restrict__ v2_b) {
    __shared__ float sqk[B * C];
    __shared__ float sv[B * 16];
    const int tid = threadIdx.x;
    for (int i = tid; i < B * C; i += 256) sqk[i] = g_qk[i];
    __syncthreads();
    const int b = tid >> 4, j = tid & 15;
    float acc = v1_b[j];
#pragma unroll 4
    for (int c = 0; c < C; c++) acc += v1_w[j * C + c] * sqk[b * C + c];
    float mu = acc;
    for (int off = 8; off; off >>= 1) mu += __shfl_xor_sync(0xffffffffu, mu, off);
    mu *= (1.f / 16.f);
    float d = acc - mu;
    float var = d * d;
    for (int off = 8; off; off >>= 1) var += __shfl_xor_sync(0xffffffffu, var, off);
    var *= (1.f / 16.f);
    float vn = d * rsqrtf(var + 1e-5f);
    vn = vn * ln_w[j] + ln_b[j];
    vn = fmaxf(vn, 0.f);
    sv[tid] = vn;
    __syncthreads();
    const int b2 = tid >> 4;
    const int jo = tid & 15;
#pragma unroll
    for (int i = 0; i < 16; i++) {
        int co = jo + (i << 4);
        float a = v2_b[co];
#pragma unroll
        for (int jj = 0; jj < 16; jj++) a += v2_w[co * 16 + jj] * sv[b2 * 16 + jj];
        g_v[b2 * C + co] = a;
    }
}

// =====================================================================
// K7: out = ctx_all + v (broadcast over H,W)
// =====================================================================
__global__ __launch_bounds__(256) void k_final(float* __restrict__ out) {
    const int idx4 = blockIdx.x * 256 + threadIdx.x;
    const size_t base = (size_t)idx4 << 2;
    const int bc = (int)(base >> 12);
    const float vv = g_v[bc];
    float4 t = *(const float4*)&g_ctxall[base];
    t.x += vv; t.y += vv; t.z += vv; t.w += vv;
    *(float4*)&out[base] = t;
}

// =====================================================================
extern "C" void kernel_launch(void* const* d_in, const int* in_sizes, int n_in,
                              void* d_out, int out_size) {
    const float* x      = (const float*)d_in[0];
    const float* conv_w = (const float*)d_in[1];
    const float* conv_b = (const float*)d_in[2];
    const float* fw3    = (const float*)d_in[3];
    const float* fw5    = (const float*)d_in[4];
    const float* fw7    = (const float*)d_in[5];
    const float* key_w  = (const float*)d_in[6];
    const float* key_b  = (const float*)d_in[7];
    const float* v1_w   = (const float*)d_in[8];
    const float* v1_b   = (const float*)d_in[9];
    const float* ln_w   = (const float*)d_in[10];
    const float* ln_b   = (const float*)d_in[11];
    const float* v2_w   = (const float*)d_in[12];
    const float* v2_b   = (const float*)d_in[13];

    static bool attr_set = false;
    if (!attr_set) {
        cudaFuncSetAttribute(k_gemm, cudaFuncAttributeMaxDynamicSharedMemorySize, GEMM_SMEM);
        attr_set = true;
    }

    k_wsplit<<<256, 256>>>(conv_w);
    k_gemm<<<1024, 256, GEMM_SMEM>>>(x);
    k_gates<<<1024, 256>>>(x, conv_w, conv_b);
    k_dwchain<<<4096, 256>>>(fw3, fw5, fw7, conv_b);
    k_keylogit<<<64, 256>>>(key_w, key_b);
    k_softmax<<<16, 256>>>();
    k_qk<<<4096, 256>>>();
    k_vmlp<<<1, 256>>>(v1_w, v1_b, ln_w, ln_b, v2_w, v2_b);
    k_final<<<16384, 256>>>((float*)d_out);
}